// round 1
// baseline (speedup 1.0000x reference)
#include <cuda_runtime.h>
#include <math.h>

#define HC 128
#define N2MAX 96000

// ---------------- scratch (static device globals; no allocation) ----------------
__device__ __align__(16) float g_A[N2MAX * HC];
__device__ __align__(16) float g_B[N2MAX * HC];
__device__ __align__(16) float g_C[N2MAX * HC];
__device__ float g_dinv[N2MAX];
__device__ float g_tp0[16000 * 3];
__device__ float g_tp1[32000 * 3];
__device__ float g_tp2[96000 * 3];
__device__ float g_pp2[32000];      // |p|^2 of candidate points (max 32000)
__device__ int   g_idx[N2MAX * 3];
__device__ float g_d2[N2MAX * 3];

// ---------------- kernels ----------------

__global__ void transform_kernel(const float* __restrict__ pos, int n, float* __restrict__ out) {
    int i = blockIdx.x * blockDim.x + threadIdx.x;
    if (i >= n) return;
    float x = pos[3 * i], y = pos[3 * i + 1], z = pos[3 * i + 2];
    float nx = x - 0.57735026918962576f * y;               // x - tan(30deg)*y
    float s = 1.0f + 0.78571428571428571f * (y / 1.1963f); // 1 + (1/0.56-1)*(y/1.1963)
    out[3 * i]     = nx * s;
    out[3 * i + 1] = y * s;
    out[3 * i + 2] = z * s;
}

__global__ void sqnorm_kernel(const float* __restrict__ p, int n, float* __restrict__ o) {
    int i = blockIdx.x * blockDim.x + threadIdx.x;
    if (i >= n) return;
    float x = p[3 * i], y = p[3 * i + 1], z = p[3 * i + 2];
    o[i] = x * x + y * y + z * z;
}

__device__ __forceinline__ float selu_f(float v) {
    const float alpha = 1.6732632423543772f;
    const float scale = 1.0507009873554805f;
    return scale * (v > 0.f ? v : alpha * expm1f(v));
}

// x = selu(latent @ W_lin + b_lin), latent [n,64], W [64,128]
__global__ void linear_selu_kernel(const float* __restrict__ latent, const float* __restrict__ W,
                                   const float* __restrict__ b, int n, float* __restrict__ out) {
    __shared__ float s[64];
    int node = blockIdx.x;
    int tid = threadIdx.x;
    if (tid < 64) s[tid] = latent[node * 64 + tid];
    __syncthreads();
    float acc = b[tid];
#pragma unroll 8
    for (int k = 0; k < 64; k++) acc = fmaf(s[k], W[k * HC + tid], acc);
    out[node * HC + tid] = selu_f(acc);
}

__global__ void fill1_kernel(float* __restrict__ d, int n) {
    int i = blockIdx.x * blockDim.x + threadIdx.x;
    if (i < n) d[i] = 1.0f; // self-loop
}

__global__ void degcount_kernel(const int* __restrict__ col, int E, float* __restrict__ deg) {
    int e = blockIdx.x * blockDim.x + threadIdx.x;
    if (e < E) atomicAdd(&deg[col[e]], 1.0f);
}

__global__ void dinv_kernel(float* __restrict__ d, int n) {
    int i = blockIdx.x * blockDim.x + threadIdx.x;
    if (i < n) d[i] = rsqrtf(d[i]);
}

// xw = concat(x, pos) @ W   (x [n,128], pos [n,3], W [131,128])
__global__ void __launch_bounds__(128) gemm128_kernel(
    const float* __restrict__ x, const float* __restrict__ pos,
    const float* __restrict__ W, int n, float* __restrict__ xw) {
    const int NT = 16;
    __shared__ float sIn[NT][132];
    int base = blockIdx.x * NT;
    int tid = threadIdx.x;
    for (int i = tid; i < NT * 131; i += 128) {
        int r = i / 131, c = i - r * 131;
        int node = base + r;
        float v = 0.f;
        if (node < n) v = (c < 128) ? x[node * 128 + c] : pos[node * 3 + (c - 128)];
        sIn[r][c] = v;
    }
    __syncthreads();
    float acc[NT];
#pragma unroll
    for (int j = 0; j < NT; j++) acc[j] = 0.f;
    for (int k = 0; k < 131; k++) {
        float w = W[k * 128 + tid];
#pragma unroll
        for (int j = 0; j < NT; j++) acc[j] = fmaf(sIn[j][k], w, acc[j]);
    }
#pragma unroll
    for (int j = 0; j < NT; j++) {
        int node = base + j;
        if (node < n) xw[node * 128 + tid] = acc[j];
    }
}

// acc = xw * dinv^2 + b  (self-loop term + bias, also serves as init)
__global__ void selfinit_kernel(const float* __restrict__ xw, const float* __restrict__ dinv,
                                const float* __restrict__ b, int n, float* __restrict__ acc) {
    int i = blockIdx.x * blockDim.x + threadIdx.x;
    if (i >= n * HC) return;
    int node = i >> 7, c = i & 127;
    float s = dinv[node];
    acc[i] = fmaf(xw[i], s * s, b[c]);
}

// acc[col] += xw[row] * dinv[row]*dinv[col]  over edges, 128 channels (float4 RED)
__global__ void scatter128_kernel(const float4* __restrict__ xw4, const float* __restrict__ dinv,
                                  const int* __restrict__ row, const int* __restrict__ col,
                                  int E, float4* __restrict__ acc4) {
    int gid = blockIdx.x * blockDim.x + threadIdx.x;
    int e = gid >> 5;
    int j = gid & 31;
    if (e >= E) return;
    int r = row[e], c = col[e];
    float nrm = dinv[r] * dinv[c];
    float4 v = xw4[r * 32 + j];
    v.x *= nrm; v.y *= nrm; v.z *= nrm; v.w *= nrm;
    float* dst = (float*)&acc4[c * 32 + j];
    asm volatile("red.global.add.v4.f32 [%0], {%1,%2,%3,%4};"
                 :: "l"(dst), "f"(v.x), "f"(v.y), "f"(v.z), "f"(v.w) : "memory");
}

__global__ void selu_kernel(const float* __restrict__ in, int total, float* __restrict__ out) {
    int i = blockIdx.x * blockDim.x + threadIdx.x;
    if (i < total) out[i] = selu_f(in[i]);
}

// brute-force top-3 NN: queries q [nq,3] against points p [np,3] with |p|^2 precomputed
__global__ void __launch_bounds__(128) knn_kernel(
    const float* __restrict__ q, int nq,
    const float* __restrict__ p, const float* __restrict__ p2, int np,
    int* __restrict__ oidx, float* __restrict__ od2) {
    const int TS = 1024;
    __shared__ float sx[TS], sy[TS], sz[TS], s2[TS];
    int qi = blockIdx.x * blockDim.x + threadIdx.x;
    float q0 = 0.f, q1 = 0.f, q2v = 0.f, qq = 0.f;
    if (qi < nq) {
        q0 = q[qi * 3]; q1 = q[qi * 3 + 1]; q2v = q[qi * 3 + 2];
        qq = q0 * q0;
        qq = fmaf(q1, q1, qq);
        qq = fmaf(q2v, q2v, qq);
    }
    float b0 = 1e30f, b1 = 1e30f, b2 = 1e30f;
    int i0 = 0, i1 = 0, i2 = 0;
    for (int t0 = 0; t0 < np; t0 += TS) {
        int cnt = min(TS, np - t0);
        __syncthreads();
        for (int i = threadIdx.x; i < cnt; i += blockDim.x) {
            int g = t0 + i;
            sx[i] = p[g * 3]; sy[i] = p[g * 3 + 1]; sz[i] = p[g * 3 + 2]; s2[i] = p2[g];
        }
        __syncthreads();
#pragma unroll 4
        for (int i = 0; i < cnt; i++) {
            float dot = q0 * sx[i];
            dot = fmaf(q1, sy[i], dot);
            dot = fmaf(q2v, sz[i], dot);
            float d = fmaf(-2.0f, dot, qq) + s2[i];
            if (d < b2) {
                int gidx = t0 + i;
                if (d < b0)       { b2 = b1; i2 = i1; b1 = b0; i1 = i0; b0 = d; i0 = gidx; }
                else if (d < b1)  { b2 = b1; i2 = i1; b1 = d;  i1 = gidx; }
                else              { b2 = d;  i2 = gidx; }
            }
        }
    }
    if (qi < nq) {
        oidx[qi * 3] = i0; oidx[qi * 3 + 1] = i1; oidx[qi * 3 + 2] = i2;
        od2[qi * 3] = b0;  od2[qi * 3 + 1] = b1;  od2[qi * 3 + 2] = b2;
    }
}

// inverse-squared-distance weighted interpolation: out[q] = sum_k w_k x[idx_k] / sum w
__global__ void interp_kernel(const float* __restrict__ x, const int* __restrict__ idx,
                              const float* __restrict__ d2, int nq, float* __restrict__ out) {
    int qi = blockIdx.x;
    int c = threadIdx.x;
    float w0 = 1.0f / fmaxf(d2[qi * 3],     1e-16f);
    float w1 = 1.0f / fmaxf(d2[qi * 3 + 1], 1e-16f);
    float w2 = 1.0f / fmaxf(d2[qi * 3 + 2], 1e-16f);
    int i0 = idx[qi * 3], i1 = idx[qi * 3 + 1], i2 = idx[qi * 3 + 2];
    float num = w0 * x[i0 * 128 + c];
    num = fmaf(w1, x[i1 * 128 + c], num);
    num = fmaf(w2, x[i2 * 128 + c], num);
    out[qi * 128 + c] = num / (w0 + w1 + w2);
}

// final conv GEMM: xw5 = concat(x, pos) @ W4, W4 [131,5]
__global__ void __launch_bounds__(128) gemm5_kernel(
    const float* __restrict__ x, const float* __restrict__ pos,
    const float* __restrict__ W, int n, float* __restrict__ xw) {
    const int NT = 25;
    __shared__ float sIn[NT][132];
    __shared__ float sW[131 * 5];
    int tid = threadIdx.x;
    for (int i = tid; i < 131 * 5; i += 128) sW[i] = W[i];
    int base = blockIdx.x * NT;
    for (int i = tid; i < NT * 131; i += 128) {
        int r = i / 131, c = i - r * 131;
        int node = base + r;
        float v = 0.f;
        if (node < n) v = (c < 128) ? x[node * 128 + c] : pos[node * 3 + (c - 128)];
        sIn[r][c] = v;
    }
    __syncthreads();
    if (tid < 125) {
        int r = tid / 5, c = tid - r * 5;
        int node = base + r;
        float acc = 0.f;
        for (int k = 0; k < 131; k++) acc = fmaf(sIn[r][k], sW[k * 5 + c], acc);
        if (node < n) xw[node * 5 + c] = acc;
    }
}

__global__ void selfinit5_kernel(const float* __restrict__ xw, const float* __restrict__ dinv,
                                 const float* __restrict__ b, int n, float* __restrict__ acc) {
    int i = blockIdx.x * blockDim.x + threadIdx.x;
    if (i >= n * 5) return;
    int node = i / 5, c = i - node * 5;
    float s = dinv[node];
    acc[i] = fmaf(xw[i], s * s, b[c]);
}

__global__ void scatter5_kernel(const float* __restrict__ xw, const float* __restrict__ dinv,
                                const int* __restrict__ row, const int* __restrict__ col,
                                int E, float* __restrict__ acc) {
    int gid = blockIdx.x * blockDim.x + threadIdx.x;
    int e = gid / 5;
    int j = gid - e * 5;
    if (e >= E) return;
    int r = row[e], c = col[e];
    atomicAdd(&acc[c * 5 + j], xw[r * 5 + j] * dinv[r] * dinv[c]);
}

// ---------------- orchestration ----------------

static inline int cdiv(int a, int b) { return (a + b - 1) / b; }

extern "C" void kernel_launch(void* const* d_in, const int* in_sizes, int n_in,
                              void* d_out, int out_size) {
    const float* latent = (const float*)d_in[0];
    const float* pos0 = (const float*)d_in[1];
    const float* pos1 = (const float*)d_in[2];
    const float* pos2 = (const float*)d_in[3];
    const float* Wlin = (const float*)d_in[4];
    const float* blin = (const float*)d_in[5];
    const float* W0 = (const float*)d_in[6];  const float* b0 = (const float*)d_in[7];
    const float* W1 = (const float*)d_in[8];  const float* b1 = (const float*)d_in[9];
    const float* W2 = (const float*)d_in[10]; const float* b2 = (const float*)d_in[11];
    const float* W3 = (const float*)d_in[12]; const float* b3 = (const float*)d_in[13];
    const float* W4 = (const float*)d_in[14]; const float* b4 = (const float*)d_in[15];
    const int* e0 = (const int*)d_in[16];
    const int* e1 = (const int*)d_in[17];
    const int* e2 = (const int*)d_in[18];
    float* out = (float*)d_out;

    int N0 = in_sizes[1] / 3, N1 = in_sizes[2] / 3, N2 = in_sizes[3] / 3;
    int E0 = in_sizes[16] / 2, E1 = in_sizes[17] / 2, E2 = in_sizes[18] / 2;

    float *A, *B, *C, *dinv, *tp0, *tp1, *tp2, *pp2, *d2f;
    int* idx;
    cudaGetSymbolAddress((void**)&A, g_A);
    cudaGetSymbolAddress((void**)&B, g_B);
    cudaGetSymbolAddress((void**)&C, g_C);
    cudaGetSymbolAddress((void**)&dinv, g_dinv);
    cudaGetSymbolAddress((void**)&tp0, g_tp0);
    cudaGetSymbolAddress((void**)&tp1, g_tp1);
    cudaGetSymbolAddress((void**)&tp2, g_tp2);
    cudaGetSymbolAddress((void**)&pp2, g_pp2);
    cudaGetSymbolAddress((void**)&idx, g_idx);
    cudaGetSymbolAddress((void**)&d2f, g_d2);

    // position transforms
    transform_kernel<<<cdiv(N0, 256), 256>>>(pos0, N0, tp0);
    transform_kernel<<<cdiv(N1, 256), 256>>>(pos1, N1, tp1);
    transform_kernel<<<cdiv(N2, 256), 256>>>(pos2, N2, tp2);

    // x = selu(latent @ Wlin + blin)  -> A
    linear_selu_kernel<<<N0, 128>>>(latent, Wlin, blin, N0, A);

    // level-0 dinv (shared by conv0, conv1)
    fill1_kernel<<<cdiv(N0, 256), 256>>>(dinv, N0);
    degcount_kernel<<<cdiv(E0, 256), 256>>>(e0 + E0, E0, dinv);
    dinv_kernel<<<cdiv(N0, 256), 256>>>(dinv, N0);

    // conv0: A -> A
    gemm128_kernel<<<cdiv(N0, 16), 128>>>(A, pos0, W0, N0, B);
    selfinit_kernel<<<cdiv(N0 * HC, 256), 256>>>(B, dinv, b0, N0, C);
    scatter128_kernel<<<cdiv(E0 * 32, 256), 256>>>((const float4*)B, dinv, e0, e0 + E0, E0, (float4*)C);
    selu_kernel<<<cdiv(N0 * HC, 256), 256>>>(C, N0 * HC, A);

    // conv1: A -> A
    gemm128_kernel<<<cdiv(N0, 16), 128>>>(A, pos0, W1, N0, B);
    selfinit_kernel<<<cdiv(N0 * HC, 256), 256>>>(B, dinv, b1, N0, C);
    scatter128_kernel<<<cdiv(E0 * 32, 256), 256>>>((const float4*)B, dinv, e0, e0 + E0, E0, (float4*)C);
    selu_kernel<<<cdiv(N0 * HC, 256), 256>>>(C, N0 * HC, A);

    // interp level 0 -> 1: A(N0) -> B(N1)
    sqnorm_kernel<<<cdiv(N0, 256), 256>>>(tp0, N0, pp2);
    knn_kernel<<<cdiv(N1, 128), 128>>>(tp1, N1, tp0, pp2, N0, idx, d2f);
    interp_kernel<<<N1, 128>>>(A, idx, d2f, N1, B);

    // level-1 dinv
    fill1_kernel<<<cdiv(N1, 256), 256>>>(dinv, N1);
    degcount_kernel<<<cdiv(E1, 256), 256>>>(e1 + E1, E1, dinv);
    dinv_kernel<<<cdiv(N1, 256), 256>>>(dinv, N1);

    // conv2: B -> B
    gemm128_kernel<<<cdiv(N1, 16), 128>>>(B, pos1, W2, N1, A);
    selfinit_kernel<<<cdiv(N1 * HC, 256), 256>>>(A, dinv, b2, N1, C);
    scatter128_kernel<<<cdiv(E1 * 32, 256), 256>>>((const float4*)A, dinv, e1, e1 + E1, E1, (float4*)C);
    selu_kernel<<<cdiv(N1 * HC, 256), 256>>>(C, N1 * HC, B);

    // interp level 1 -> 2: B(N1) -> A(N2)
    sqnorm_kernel<<<cdiv(N1, 256), 256>>>(tp1, N1, pp2);
    knn_kernel<<<cdiv(N2, 128), 128>>>(tp2, N2, tp1, pp2, N1, idx, d2f);
    interp_kernel<<<N2, 128>>>(B, idx, d2f, N2, A);

    // level-2 dinv (shared by conv3, conv4)
    fill1_kernel<<<cdiv(N2, 256), 256>>>(dinv, N2);
    degcount_kernel<<<cdiv(E2, 256), 256>>>(e2 + E2, E2, dinv);
    dinv_kernel<<<cdiv(N2, 256), 256>>>(dinv, N2);

    // conv3: A -> A
    gemm128_kernel<<<cdiv(N2, 16), 128>>>(A, pos2, W3, N2, B);
    selfinit_kernel<<<cdiv(N2 * HC, 256), 256>>>(B, dinv, b3, N2, C);
    scatter128_kernel<<<cdiv(E2 * 32, 256), 256>>>((const float4*)B, dinv, e2, e2 + E2, E2, (float4*)C);
    selu_kernel<<<cdiv(N2 * HC, 256), 256>>>(C, N2 * HC, A);

    // conv4 (no selu): A -> out [N2,5]
    gemm5_kernel<<<cdiv(N2, 25), 128>>>(A, pos2, W4, N2, B);
    selfinit5_kernel<<<cdiv(N2 * 5, 256), 256>>>(B, dinv, b4, N2, out);
    scatter5_kernel<<<cdiv(E2 * 5, 256), 256>>>(B, dinv, e2, e2 + E2, E2, out);
}

// round 2
// speedup vs baseline: 2.4431x; 2.4431x over previous
#include <cuda_runtime.h>
#include <math.h>

#define HC 128
#define N2MAX 96000
#define MAXCELLS 65536
#define MAXPTS 32000

// ---------------- scratch (static device globals; no allocation) ----------------
__device__ __align__(16) float g_A[N2MAX * HC];
__device__ __align__(16) float g_B[N2MAX * HC];
__device__ __align__(16) float g_C[N2MAX * HC];
__device__ float g_dinv[N2MAX];
__device__ float g_tp0[16000 * 3];
__device__ float g_tp1[32000 * 3];
__device__ float g_tp2[96000 * 3];
__device__ int   g_idx[N2MAX * 3];
__device__ float g_d2[N2MAX * 3];

// grid kNN scratch
__device__ unsigned g_bbox0[6];
__device__ unsigned g_bbox1[6];
struct GridParams { float ox, oy, oz, h, invh; int Gx, Gy, Gz, Rmax; };
__device__ GridParams g_gp;
__device__ int g_cellCount[MAXCELLS];
__device__ int g_cellStart[MAXCELLS + 1];
__device__ int g_cursor[MAXCELLS];
__device__ __align__(16) float4 g_spts[MAXPTS];
__device__ int g_sidx[MAXPTS];

// ---------------- helpers ----------------
__device__ __forceinline__ unsigned fkey(float f) {
    unsigned u = __float_as_uint(f);
    return (u & 0x80000000u) ? ~u : (u | 0x80000000u);
}
__device__ __forceinline__ float fdec(unsigned k) {
    return (k & 0x80000000u) ? __uint_as_float(k ^ 0x80000000u) : __uint_as_float(~k);
}
__device__ __forceinline__ float selu_f(float v) {
    const float alpha = 1.6732632423543772f;
    const float scale = 1.0507009873554805f;
    return scale * (v > 0.f ? v : alpha * expm1f(v));
}

// ---------------- kernels ----------------

__global__ void initbbox_kernel() {
    int i = threadIdx.x;
    if (i < 6)  g_bbox0[i] = (i < 3) ? 0xFFFFFFFFu : 0u;
    if (i < 6)  g_bbox1[i] = (i < 3) ? 0xFFFFFFFFu : 0u;
}

// transform + (optional) bbox reduction of the transformed points
__global__ void transform_kernel(const float* __restrict__ pos, int n,
                                 float* __restrict__ out, unsigned* bbox) {
    int i = blockIdx.x * blockDim.x + threadIdx.x;
    bool valid = (i < n);
    float x = 0.f, y = 0.f, z = 0.f;
    if (valid) { x = pos[3 * i]; y = pos[3 * i + 1]; z = pos[3 * i + 2]; }
    float nx = x - 0.57735026918962576f * y;
    float s = 1.0f + 0.78571428571428571f * (y / 1.1963f);
    float ox = nx * s, oy = y * s, oz = z * s;
    if (valid) { out[3 * i] = ox; out[3 * i + 1] = oy; out[3 * i + 2] = oz; }
    if (bbox) {
        unsigned kx = valid ? fkey(ox) : 0xFFFFFFFFu;
        unsigned ky = valid ? fkey(oy) : 0xFFFFFFFFu;
        unsigned kz = valid ? fkey(oz) : 0xFFFFFFFFu;
        unsigned mnx = __reduce_min_sync(0xFFFFFFFFu, kx);
        unsigned mny = __reduce_min_sync(0xFFFFFFFFu, ky);
        unsigned mnz = __reduce_min_sync(0xFFFFFFFFu, kz);
        unsigned mxx = __reduce_max_sync(0xFFFFFFFFu, valid ? kx : 0u);
        unsigned mxy = __reduce_max_sync(0xFFFFFFFFu, valid ? ky : 0u);
        unsigned mxz = __reduce_max_sync(0xFFFFFFFFu, valid ? kz : 0u);
        if ((threadIdx.x & 31) == 0) {
            atomicMin(&bbox[0], mnx); atomicMin(&bbox[1], mny); atomicMin(&bbox[2], mnz);
            atomicMax(&bbox[3], mxx); atomicMax(&bbox[4], mxy); atomicMax(&bbox[5], mxz);
        }
    }
}

__global__ void gridparams_kernel(const unsigned* __restrict__ bbox, int np) {
    if (threadIdx.x != 0 || blockIdx.x != 0) return;
    float ox = fdec(bbox[0]), oy = fdec(bbox[1]), oz = fdec(bbox[2]);
    float mx = fdec(bbox[3]), my = fdec(bbox[4]), mz = fdec(bbox[5]);
    float ex = mx - ox, ey = my - oy, ez = mz - oz;
    float em = fmaxf(ex, fmaxf(ey, ez));
    float eps = 1e-4f * em + 1e-6f;
    ox -= eps; oy -= eps; oz -= eps;
    ex += 2.f * eps; ey += 2.f * eps; ez += 2.f * eps;
    int target = np / 2; if (target < 1) target = 1;
    float h = cbrtf(ex * ey * ez / (float)target);
    if (h < 1e-6f) h = 1e-6f;
    int Gx, Gy, Gz;
    for (int it = 0; it < 64; it++) {
        Gx = (int)(ex / h) + 1; Gy = (int)(ey / h) + 1; Gz = (int)(ez / h) + 1;
        if (Gx < 1) Gx = 1; if (Gy < 1) Gy = 1; if (Gz < 1) Gz = 1;
        long long prod = (long long)Gx * Gy * Gz;
        if (prod <= MAXCELLS) break;
        h *= 1.0905f;
    }
    GridParams gp;
    gp.ox = ox; gp.oy = oy; gp.oz = oz; gp.h = h; gp.invh = 1.0f / h;
    gp.Gx = Gx; gp.Gy = Gy; gp.Gz = Gz;
    gp.Rmax = max(Gx, max(Gy, Gz));
    g_gp = gp;
}

__global__ void zerocells_kernel() {
    int i = blockIdx.x * blockDim.x + threadIdx.x;
    if (i < MAXCELLS) g_cellCount[i] = 0;
}

__device__ __forceinline__ int cell_of(float x, float y, float z, const GridParams& gp) {
    int cx = (int)floorf((x - gp.ox) * gp.invh);
    int cy = (int)floorf((y - gp.oy) * gp.invh);
    int cz = (int)floorf((z - gp.oz) * gp.invh);
    cx = min(max(cx, 0), gp.Gx - 1);
    cy = min(max(cy, 0), gp.Gy - 1);
    cz = min(max(cz, 0), gp.Gz - 1);
    return (cz * gp.Gy + cy) * gp.Gx + cx;
}

__global__ void gridcount_kernel(const float* __restrict__ p, int np) {
    int i = blockIdx.x * blockDim.x + threadIdx.x;
    if (i >= np) return;
    GridParams gp = g_gp;
    int c = cell_of(p[3 * i], p[3 * i + 1], p[3 * i + 2], gp);
    atomicAdd(&g_cellCount[c], 1);
}

__global__ void __launch_bounds__(1024) gridscan_kernel() {
    __shared__ int ssum[1024];
    int tid = threadIdx.x;
    const int PER = MAXCELLS / 1024;
    int base = tid * PER;
    int sum = 0;
    for (int i = 0; i < PER; i++) sum += g_cellCount[base + i];
    ssum[tid] = sum;
    __syncthreads();
    for (int off = 1; off < 1024; off <<= 1) {
        int v = (tid >= off) ? ssum[tid - off] : 0;
        __syncthreads();
        ssum[tid] += v;
        __syncthreads();
    }
    int run = ssum[tid] - sum;  // exclusive prefix
    for (int i = 0; i < PER; i++) {
        g_cellStart[base + i] = run;
        g_cursor[base + i] = run;
        run += g_cellCount[base + i];
    }
    if (tid == 1023) g_cellStart[MAXCELLS] = run;
}

__global__ void gridscatter_kernel(const float* __restrict__ p, int np) {
    int i = blockIdx.x * blockDim.x + threadIdx.x;
    if (i >= np) return;
    GridParams gp = g_gp;
    float x = p[3 * i], y = p[3 * i + 1], z = p[3 * i + 2];
    int c = cell_of(x, y, z, gp);
    int pos = atomicAdd(&g_cursor[c], 1);
    float p2 = x * x;
    p2 = fmaf(y, y, p2);
    p2 = fmaf(z, z, p2);
    g_spts[pos] = make_float4(x, y, z, p2);
    g_sidx[pos] = i;
}

#define KNN_SCAN_SPAN(S_, E_)                                                   \
    for (int j_ = (S_); j_ < (E_); j_++) {                                      \
        float4 pt = g_spts[j_];                                                 \
        float dot = qx * pt.x;                                                  \
        dot = fmaf(qy, pt.y, dot);                                              \
        dot = fmaf(qz, pt.z, dot);                                              \
        float d = fmaf(-2.0f, dot, qq) + pt.w;                                  \
        if (d < b2) {                                                           \
            int gi = g_sidx[j_];                                                \
            if (d < b0)      { b2 = b1; i2 = i1; b1 = b0; i1 = i0; b0 = d; i0 = gi; } \
            else if (d < b1) { b2 = b1; i2 = i1; b1 = d; i1 = gi; }             \
            else             { b2 = d; i2 = gi; }                               \
        }                                                                       \
    }

__global__ void __launch_bounds__(128) gridknn_kernel(
    const float* __restrict__ q, int nq,
    int* __restrict__ oidx, float* __restrict__ od2) {
    int qi = blockIdx.x * blockDim.x + threadIdx.x;
    if (qi >= nq) return;
    GridParams gp = g_gp;
    float qx = q[3 * qi], qy = q[3 * qi + 1], qz = q[3 * qi + 2];
    float qq = qx * qx;
    qq = fmaf(qy, qy, qq);
    qq = fmaf(qz, qz, qq);
    int ccx = (int)floorf((qx - gp.ox) * gp.invh);
    int ccy = (int)floorf((qy - gp.oy) * gp.invh);
    int ccz = (int)floorf((qz - gp.oz) * gp.invh);
    ccx = min(max(ccx, 0), gp.Gx - 1);
    ccy = min(max(ccy, 0), gp.Gy - 1);
    ccz = min(max(ccz, 0), gp.Gz - 1);

    float b0 = 1e30f, b1 = 1e30f, b2 = 1e30f;
    int i0 = 0, i1 = 0, i2 = 0;

    // ring 0
    {
        int c = (ccz * gp.Gy + ccy) * gp.Gx + ccx;
        int s = g_cellStart[c], e = g_cellStart[c + 1];
        KNN_SCAN_SPAN(s, e);
    }
    for (int r = 1; r <= gp.Rmax; r++) {
        float dm = (float)(r - 1) * gp.h;
        if (b2 <= dm * dm) break;
        for (int dz = -r; dz <= r; dz++) {
            int z = ccz + dz;
            if (z < 0 || z >= gp.Gz) continue;
            bool zface = (dz == -r) || (dz == r);
            for (int dy = -r; dy <= r; dy++) {
                int y = ccy + dy;
                if (y < 0 || y >= gp.Gy) continue;
                bool face = zface || (dy == -r) || (dy == r);
                int rowbase = (z * gp.Gy + y) * gp.Gx;
                if (face) {
                    int x0 = max(ccx - r, 0), x1 = min(ccx + r, gp.Gx - 1);
                    int s = g_cellStart[rowbase + x0], e = g_cellStart[rowbase + x1 + 1];
                    KNN_SCAN_SPAN(s, e);
                } else {
                    int x = ccx - r;
                    if (x >= 0) {
                        int s = g_cellStart[rowbase + x], e = g_cellStart[rowbase + x + 1];
                        KNN_SCAN_SPAN(s, e);
                    }
                    x = ccx + r;
                    if (x < gp.Gx) {
                        int s = g_cellStart[rowbase + x], e = g_cellStart[rowbase + x + 1];
                        KNN_SCAN_SPAN(s, e);
                    }
                }
            }
        }
    }
    oidx[qi * 3] = i0; oidx[qi * 3 + 1] = i1; oidx[qi * 3 + 2] = i2;
    od2[qi * 3] = b0;  od2[qi * 3 + 1] = b1;  od2[qi * 3 + 2] = b2;
}

// x = selu(latent @ W_lin + b_lin), latent [n,64], W [64,128]
__global__ void linear_selu_kernel(const float* __restrict__ latent, const float* __restrict__ W,
                                   const float* __restrict__ b, int n, float* __restrict__ out) {
    __shared__ float s[64];
    int node = blockIdx.x;
    int tid = threadIdx.x;
    if (tid < 64) s[tid] = latent[node * 64 + tid];
    __syncthreads();
    float acc = b[tid];
#pragma unroll 8
    for (int k = 0; k < 64; k++) acc = fmaf(s[k], W[k * HC + tid], acc);
    out[node * HC + tid] = selu_f(acc);
}

__global__ void fill1_kernel(float* __restrict__ d, int n) {
    int i = blockIdx.x * blockDim.x + threadIdx.x;
    if (i < n) d[i] = 1.0f;
}

__global__ void degcount_kernel(const int* __restrict__ col, int E, float* __restrict__ deg) {
    int e = blockIdx.x * blockDim.x + threadIdx.x;
    if (e < E) atomicAdd(&deg[col[e]], 1.0f);
}

__global__ void dinv_kernel(float* __restrict__ d, int n) {
    int i = blockIdx.x * blockDim.x + threadIdx.x;
    if (i < n) d[i] = rsqrtf(d[i]);
}

// xw = concat(f(x), pos) @ W ;  acc = xw * dinv^2 + b   (f = selu if seluflag)
__global__ void __launch_bounds__(128) gemm128_kernel(
    const float* __restrict__ x, const float* __restrict__ pos,
    const float* __restrict__ W, const float* __restrict__ dinv,
    const float* __restrict__ b, int n,
    float* __restrict__ xw, float* __restrict__ accout, int seluflag) {
    const int NT = 16;
    __shared__ float sIn[NT][132];
    int base = blockIdx.x * NT;
    int tid = threadIdx.x;
    for (int i = tid; i < NT * 131; i += 128) {
        int r = i / 131, c = i - r * 131;
        int node = base + r;
        float v = 0.f;
        if (node < n) {
            if (c < 128) {
                v = x[node * 128 + c];
                if (seluflag) v = selu_f(v);
            } else {
                v = pos[node * 3 + (c - 128)];
            }
        }
        sIn[r][c] = v;
    }
    __syncthreads();
    float acc[NT];
#pragma unroll
    for (int j = 0; j < NT; j++) acc[j] = 0.f;
    for (int k = 0; k < 131; k++) {
        float w = W[k * 128 + tid];
#pragma unroll
        for (int j = 0; j < NT; j++) acc[j] = fmaf(sIn[j][k], w, acc[j]);
    }
    float bb = b[tid];
#pragma unroll
    for (int j = 0; j < NT; j++) {
        int node = base + j;
        if (node < n) {
            float s = dinv[node];
            xw[node * 128 + tid] = acc[j];
            accout[node * 128 + tid] = fmaf(acc[j], s * s, bb);
        }
    }
}

// acc[col] += xw[row] * dinv[row]*dinv[col]  over edges, 128 channels (float4 RED)
__global__ void scatter128_kernel(const float4* __restrict__ xw4, const float* __restrict__ dinv,
                                  const int* __restrict__ row, const int* __restrict__ col,
                                  int E, float4* __restrict__ acc4) {
    int gid = blockIdx.x * blockDim.x + threadIdx.x;
    int e = gid >> 5;
    int j = gid & 31;
    if (e >= E) return;
    int r = row[e], c = col[e];
    float nrm = dinv[r] * dinv[c];
    float4 v = xw4[r * 32 + j];
    v.x *= nrm; v.y *= nrm; v.z *= nrm; v.w *= nrm;
    float* dst = (float*)&acc4[c * 32 + j];
    asm volatile("red.global.add.v4.f32 [%0], {%1,%2,%3,%4};"
                 :: "l"(dst), "f"(v.x), "f"(v.y), "f"(v.z), "f"(v.w) : "memory");
}

// out[q] = sum_k w_k selu(x[idx_k]) / sum w
__global__ void interp_kernel(const float* __restrict__ x, const int* __restrict__ idx,
                              const float* __restrict__ d2, int nq, float* __restrict__ out) {
    int qi = blockIdx.x;
    int c = threadIdx.x;
    float w0 = 1.0f / fmaxf(d2[qi * 3],     1e-16f);
    float w1 = 1.0f / fmaxf(d2[qi * 3 + 1], 1e-16f);
    float w2 = 1.0f / fmaxf(d2[qi * 3 + 2], 1e-16f);
    int i0 = idx[qi * 3], i1 = idx[qi * 3 + 1], i2 = idx[qi * 3 + 2];
    float num = w0 * selu_f(x[i0 * 128 + c]);
    num = fmaf(w1, selu_f(x[i1 * 128 + c]), num);
    num = fmaf(w2, selu_f(x[i2 * 128 + c]), num);
    out[qi * 128 + c] = num / (w0 + w1 + w2);
}

// final conv: xw5 = concat(selu(x), pos) @ W4 ; acc = xw5*dinv^2 + b
__global__ void __launch_bounds__(128) gemm5_kernel(
    const float* __restrict__ x, const float* __restrict__ pos,
    const float* __restrict__ W, const float* __restrict__ dinv,
    const float* __restrict__ b, int n,
    float* __restrict__ xw, float* __restrict__ accout, int seluflag) {
    const int NT = 25;
    __shared__ float sIn[NT][132];
    __shared__ float sW[131 * 5];
    int tid = threadIdx.x;
    for (int i = tid; i < 131 * 5; i += 128) sW[i] = W[i];
    int base = blockIdx.x * NT;
    for (int i = tid; i < NT * 131; i += 128) {
        int r = i / 131, c = i - r * 131;
        int node = base + r;
        float v = 0.f;
        if (node < n) {
            if (c < 128) {
                v = x[node * 128 + c];
                if (seluflag) v = selu_f(v);
            } else {
                v = pos[node * 3 + (c - 128)];
            }
        }
        sIn[r][c] = v;
    }
    __syncthreads();
    if (tid < 125) {
        int r = tid / 5, c = tid - r * 5;
        int node = base + r;
        if (node < n) {
            float acc = 0.f;
            for (int k = 0; k < 131; k++) acc = fmaf(sIn[r][k], sW[k * 5 + c], acc);
            float s = dinv[node];
            xw[node * 5 + c] = acc;
            accout[node * 5 + c] = fmaf(acc, s * s, b[c]);
        }
    }
}

__global__ void scatter5_kernel(const float* __restrict__ xw, const float* __restrict__ dinv,
                                const int* __restrict__ row, const int* __restrict__ col,
                                int E, float* __restrict__ acc) {
    int gid = blockIdx.x * blockDim.x + threadIdx.x;
    int e = gid / 5;
    int j = gid - e * 5;
    if (e >= E) return;
    int r = row[e], c = col[e];
    atomicAdd(&acc[c * 5 + j], xw[r * 5 + j] * dinv[r] * dinv[c]);
}

// ---------------- orchestration ----------------

static inline int cdiv(int a, int b) { return (a + b - 1) / b; }

static void build_grid(const float* tp, int np, const unsigned* bbox) {
    gridparams_kernel<<<1, 32>>>(bbox, np);
    zerocells_kernel<<<cdiv(MAXCELLS, 256), 256>>>();
    gridcount_kernel<<<cdiv(np, 256), 256>>>(tp, np);
    gridscan_kernel<<<1, 1024>>>();
    gridscatter_kernel<<<cdiv(np, 256), 256>>>(tp, np);
}

extern "C" void kernel_launch(void* const* d_in, const int* in_sizes, int n_in,
                              void* d_out, int out_size) {
    const float* latent = (const float*)d_in[0];
    const float* pos0 = (const float*)d_in[1];
    const float* pos1 = (const float*)d_in[2];
    const float* pos2 = (const float*)d_in[3];
    const float* Wlin = (const float*)d_in[4];
    const float* blin = (const float*)d_in[5];
    const float* W0 = (const float*)d_in[6];  const float* b0 = (const float*)d_in[7];
    const float* W1 = (const float*)d_in[8];  const float* b1 = (const float*)d_in[9];
    const float* W2 = (const float*)d_in[10]; const float* b2 = (const float*)d_in[11];
    const float* W3 = (const float*)d_in[12]; const float* b3 = (const float*)d_in[13];
    const float* W4 = (const float*)d_in[14]; const float* b4 = (const float*)d_in[15];
    const int* e0 = (const int*)d_in[16];
    const int* e1 = (const int*)d_in[17];
    const int* e2 = (const int*)d_in[18];
    float* out = (float*)d_out;

    int N0 = in_sizes[1] / 3, N1 = in_sizes[2] / 3, N2 = in_sizes[3] / 3;
    int E0 = in_sizes[16] / 2, E1 = in_sizes[17] / 2, E2 = in_sizes[18] / 2;

    float *A, *B, *C, *dinv, *tp0, *tp1, *tp2, *d2f;
    int* idx;
    unsigned *bb0, *bb1;
    cudaGetSymbolAddress((void**)&A, g_A);
    cudaGetSymbolAddress((void**)&B, g_B);
    cudaGetSymbolAddress((void**)&C, g_C);
    cudaGetSymbolAddress((void**)&dinv, g_dinv);
    cudaGetSymbolAddress((void**)&tp0, g_tp0);
    cudaGetSymbolAddress((void**)&tp1, g_tp1);
    cudaGetSymbolAddress((void**)&tp2, g_tp2);
    cudaGetSymbolAddress((void**)&idx, g_idx);
    cudaGetSymbolAddress((void**)&d2f, g_d2);
    cudaGetSymbolAddress((void**)&bb0, g_bbox0);
    cudaGetSymbolAddress((void**)&bb1, g_bbox1);

    // transforms (+ bbox of candidate sets)
    initbbox_kernel<<<1, 32>>>();
    transform_kernel<<<cdiv(N0, 256), 256>>>(pos0, N0, tp0, bb0);
    transform_kernel<<<cdiv(N1, 256), 256>>>(pos1, N1, tp1, bb1);
    transform_kernel<<<cdiv(N2, 256), 256>>>(pos2, N2, tp2, nullptr);

    // x = selu(latent @ Wlin + blin) -> A
    linear_selu_kernel<<<N0, 128>>>(latent, Wlin, blin, N0, A);

    // level-0 dinv
    fill1_kernel<<<cdiv(N0, 256), 256>>>(dinv, N0);
    degcount_kernel<<<cdiv(E0, 256), 256>>>(e0 + E0, E0, dinv);
    dinv_kernel<<<cdiv(N0, 256), 256>>>(dinv, N0);

    // conv0: A -> raw C
    gemm128_kernel<<<cdiv(N0, 16), 128>>>(A, pos0, W0, dinv, b0, N0, B, C, 0);
    scatter128_kernel<<<cdiv(E0 * 32, 256), 256>>>((const float4*)B, dinv, e0, e0 + E0, E0, (float4*)C);

    // conv1: selu(C) -> raw A
    gemm128_kernel<<<cdiv(N0, 16), 128>>>(C, pos0, W1, dinv, b1, N0, B, A, 1);
    scatter128_kernel<<<cdiv(E0 * 32, 256), 256>>>((const float4*)B, dinv, e0, e0 + E0, E0, (float4*)A);

    // interp 0 -> 1: selu(A)[N0] -> B[N1]
    build_grid(tp0, N0, bb0);
    gridknn_kernel<<<cdiv(N1, 128), 128>>>(tp1, N1, idx, d2f);
    interp_kernel<<<N1, 128>>>(A, idx, d2f, N1, B);

    // level-1 dinv
    fill1_kernel<<<cdiv(N1, 256), 256>>>(dinv, N1);
    degcount_kernel<<<cdiv(E1, 256), 256>>>(e1 + E1, E1, dinv);
    dinv_kernel<<<cdiv(N1, 256), 256>>>(dinv, N1);

    // conv2: B -> raw A
    gemm128_kernel<<<cdiv(N1, 16), 128>>>(B, pos1, W2, dinv, b2, N1, C, A, 0);
    scatter128_kernel<<<cdiv(E1 * 32, 256), 256>>>((const float4*)C, dinv, e1, e1 + E1, E1, (float4*)A);

    // interp 1 -> 2: selu(A)[N1] -> B[N2]
    build_grid(tp1, N1, bb1);
    gridknn_kernel<<<cdiv(N2, 128), 128>>>(tp2, N2, idx, d2f);
    interp_kernel<<<N2, 128>>>(A, idx, d2f, N2, B);

    // level-2 dinv
    fill1_kernel<<<cdiv(N2, 256), 256>>>(dinv, N2);
    degcount_kernel<<<cdiv(E2, 256), 256>>>(e2 + E2, E2, dinv);
    dinv_kernel<<<cdiv(N2, 256), 256>>>(dinv, N2);

    // conv3: B -> raw A
    gemm128_kernel<<<cdiv(N2, 16), 128>>>(B, pos2, W3, dinv, b3, N2, C, A, 0);
    scatter128_kernel<<<cdiv(E2 * 32, 256), 256>>>((const float4*)C, dinv, e2, e2 + E2, E2, (float4*)A);

    // conv4 (no selu on output): selu(A) -> out
    gemm5_kernel<<<cdiv(N2, 25), 128>>>(A, pos2, W4, dinv, b4, N2, C, out, 1);
    scatter5_kernel<<<cdiv(E2 * 5, 256), 256>>>(C, dinv, e2, e2 + E2, E2, out);
}